// round 7
// baseline (speedup 1.0000x reference)
#include <cuda_runtime.h>
#include <math.h>

// InterfaceBoundaryLoss: B=4, H=W=2048, DX=DY=0.01, E_IN=2, CONST=1, WEIGHT=1.
//
// With a=h-1024, b=w-1024, dd=a^2+b^2:
//   interface <=> dd <  262144           (r < 512)
//   boundary  <=> 261122 <= dd <= 263168 (|r-512| < 1)
//
// R6: octant enumeration (0 <= a <= b, rows a=0..362, 8 reflections x 4
// batches = 32 lanes per pixel) + atomic-tail removal:
//   - nb computed exactly on HOST, 1/(4 nb) passed as arg (no count atomics)
//   - per-block partial via plain STG to a slot; only a ticket atomicInc
//   - 46 blocks x 8 warps (halved ticket contention vs 91 blocks)

#define WW 2048
#define HWSZ (2048 * 2048)
#define TH  262144
#define LOQ 261122
#define HIQ 263168
#define NROWS 363
#define WARPS_PER_BLK 8
#define NBLOCKS ((NROWS + WARPS_PER_BLK - 1) / WARPS_PER_BLK)   // 46

__device__ float        g_part[NBLOCKS];
__device__ unsigned int g_done = 0u;

__global__ void __launch_bounds__(WARPS_PER_BLK * 32)
ibl_kernel(const float* __restrict__ s1, const float* __restrict__ s2,
           float* __restrict__ out, double inv)
{
    const int tid  = threadIdx.x;
    const int lane = tid & 31;
    const int wid  = tid >> 5;
    const int a    = blockIdx.x * WARPS_PER_BLK + wid;   // octant row

    float lacc = 0.0f;

    if (a < NROWS) {
        const int lo = LOQ - a * a;            // > 0 for a <= 362
        const int hi = HIQ - a * a;

        // bmax = floor(sqrt(hi)), bminr = ceil(sqrt(lo)); FP32 + exact fixup
        int bmax = (int)sqrtf((float)hi);
        while ((bmax + 1) * (bmax + 1) <= hi) ++bmax;
        while (bmax * bmax > hi) --bmax;
        int bminr = (int)sqrtf((float)lo);
        while (bminr * bminr < lo) ++bminr;
        while ((bminr - 1) * (bminr - 1) >= lo) --bminr;
        const int bmin = (bminr > a) ? bminr : a;   // octant: b >= a
        const int Wd   = bmax - bmin + 1;           // 1..3

        const int refl = lane & 7;
        const int bb   = lane >> 3;                 // batch 0..3
        const int sg1  = (refl & 1) ? -1 : 1;
        const int sg2  = (refl & 2) ? -1 : 1;
        const int sw   = refl >> 2;

        const int planeoff = bb * HWSZ;

        #pragma unroll
        for (int p = 0; p < 4; ++p) {
            const int b = bmin + p;
            // duplicate-free reflection mask
            bool nodup;
            if (a == 0)       nodup = sw ? (sg2 > 0) : (sg1 > 0);
            else if (a == b)  nodup = (sw == 0);
            else              nodup = true;
            const bool act = (p < Wd) && nodup;
            const float w  = act ? 1.0f : 0.0f;

            const int x0 = sw ? b : a;
            const int y0 = sw ? a : b;
            const int x  = sg1 * x0;               // h - 1024
            const int y  = sg2 * y0;               // w - 1024

            const int dd = x * x + y * y;
            const bool c  = dd < TH;
            const bool pu = ((((x - 1) * (x - 1) + y * y) < TH) == c);
            const bool pd = ((((x + 1) * (x + 1) + y * y) < TH) == c);
            const bool pl = (((x * x + (y - 1) * (y - 1)) < TH) == c);
            const bool pr = (((x * x + (y + 1) * (y + 1)) < TH) == c);
            const int voff = pu ? -WW : (pd ? WW : 0);   // 0 -> grad = 0
            const int hoff = pl ? -1  : (pr ? 1  : 0);

            const int idx = (x + 1024) * WW + (y + 1024) + planeoff;
            const float o1  = __ldg(s1 + idx);
            const float o1v = __ldg(s1 + idx + voff);
            const float o1h = __ldg(s1 + idx + hoff);
            const float o2  = __ldg(s2 + idx);
            const float o2v = __ldg(s2 + idx + voff);
            const float o2h = __ldg(s2 + idx + hoff);

            const float dv = o1 - o2;
            float f = dv * dv;
            float g, t;
            g = (o1 - o1v) * 100.0f;  t = fmaf(2.0f, g, -1.0f);  f = fmaf(t, t, f);
            g = (o1 - o1h) * 100.0f;  t = fmaf(2.0f, g, -1.0f);  f = fmaf(t, t, f);
            g = (o2 - o2v) * 100.0f;  t = fmaf(2.0f, g, -1.0f);  f = fmaf(t, t, f);
            g = (o2 - o2h) * 100.0f;  t = fmaf(2.0f, g, -1.0f);  f = fmaf(t, t, f);

            lacc = fmaf(w, f, lacc);
        }
    }

    // ---- warp reduce (float) ----
    #pragma unroll
    for (int o = 16; o > 0; o >>= 1)
        lacc += __shfl_down_sync(0xffffffffu, lacc, o);

    __shared__ float sacc[WARPS_PER_BLK];
    if (lane == 0) sacc[wid] = lacc;
    __syncthreads();
    if (wid == 0 && lane < WARPS_PER_BLK) {
        lacc = sacc[lane];
        #pragma unroll
        for (int o = WARPS_PER_BLK / 2; o > 0; o >>= 1)
            lacc += __shfl_down_sync(0x000000ffu, lacc, o);
        if (lane == 0) {
            g_part[blockIdx.x] = lacc;             // plain store, no atomic
            __threadfence();
            const unsigned int old = atomicInc(&g_done, NBLOCKS - 1u);
            if (old == NBLOCKS - 1u) {             // last block finalizes
                double tot = 0.0;
                #pragma unroll
                for (int i = 0; i < NBLOCKS; ++i)
                    tot += (double)g_part[i];      // independent loads, 1 round
                out[0] = (float)(tot * inv);
            }
        }
    }
}

extern "C" void kernel_launch(void* const* d_in, const int* in_sizes, int n_in,
                              void* d_out, int out_size)
{
    (void)in_sizes; (void)n_in; (void)out_size;
    const float* s1 = (const float*)d_in[0];
    const float* s2 = (const float*)d_in[1];
    float* out = (float*)d_out;

    // nb (boundary-pixel count) is a pure function of the geometry: compute
    // exactly on host with the same integer logic.
    long long nb = 0;
    for (int a = -512; a <= 512; ++a) {
        const int lo = LOQ - a * a;
        const int hi = HIQ - a * a;
        if (hi < 0) continue;
        int bmax = (int)floor(sqrt((double)hi));
        while ((long long)(bmax + 1) * (bmax + 1) <= hi) ++bmax;
        while ((long long)bmax * bmax > hi) --bmax;
        int bmin = 0;
        if (lo > 0) {
            bmin = (int)ceil(sqrt((double)lo));
            while ((long long)bmin * bmin < lo) ++bmin;
            while (bmin > 0 && (long long)(bmin - 1) * (bmin - 1) >= lo) --bmin;
        }
        if (bmax >= bmin)
            nb += (lo > 0) ? 2LL * (bmax - bmin + 1) : (2LL * bmax + 1);
    }
    const double inv = 1.0 / (4.0 * (double)nb);

    ibl_kernel<<<NBLOCKS, WARPS_PER_BLK * 32>>>(s1, s2, out, inv);
}

// round 8
// speedup vs baseline: 1.2657x; 1.2657x over previous
#include <cuda_runtime.h>
#include <math.h>

// InterfaceBoundaryLoss: B=4, H=W=2048, DX=DY=0.01, E_IN=2, CONST=1, WEIGHT=1.
//
// With a=h-1024, b=w-1024, dd=a^2+b^2:
//   interface <=> dd <  262144           (r < 512)
//   boundary  <=> 261122 <= dd <= 263168 (|r-512| < 1)
//
// R7 = R5 structure (91 blocks x 4 warps, octant symmetry: 0<=a<=b,
// 8 reflections x 4 batches = 32 lanes per octant pixel) with a slim tail:
//   - nb computed exactly on HOST, 1/(4 nb) passed in (no count reduction)
//   - one float atomicAdd per block (pipelines with block completion)
//   - last block: single atomicExch reads total AND resets for next replay

#define WW 2048
#define HWSZ (2048 * 2048)
#define TH  262144
#define LOQ 261122
#define HIQ 263168
#define NROWS 363
#define WARPS_PER_BLK 4
#define NBLOCKS ((NROWS + WARPS_PER_BLK - 1) / WARPS_PER_BLK)   // 91

__device__ float        g_acc  = 0.0f;
__device__ unsigned int g_done = 0u;

__global__ void __launch_bounds__(WARPS_PER_BLK * 32)
ibl_kernel(const float* __restrict__ s1, const float* __restrict__ s2,
           float* __restrict__ out, float inv)
{
    const int tid  = threadIdx.x;
    const int lane = tid & 31;
    const int wid  = tid >> 5;
    const int a    = blockIdx.x * WARPS_PER_BLK + wid;   // octant row

    float lacc = 0.0f;

    if (a < NROWS) {
        const int lo = LOQ - a * a;            // > 0 for a <= 362
        const int hi = HIQ - a * a;

        // bmax = floor(sqrt(hi)), bminr = ceil(sqrt(lo)); FP32 + exact fixup
        int bmax = (int)sqrtf((float)hi);
        while ((bmax + 1) * (bmax + 1) <= hi) ++bmax;
        while (bmax * bmax > hi) --bmax;
        int bminr = (int)sqrtf((float)lo);
        while (bminr * bminr < lo) ++bminr;
        while ((bminr - 1) * (bminr - 1) >= lo) --bminr;
        const int bmin = (bminr > a) ? bminr : a;   // octant: b >= a
        const int Wd   = bmax - bmin + 1;           // 1..3

        const int refl = lane & 7;
        const int bb   = lane >> 3;                 // batch 0..3
        const int sg1  = (refl & 1) ? -1 : 1;
        const int sg2  = (refl & 2) ? -1 : 1;
        const int sw   = refl >> 2;

        const int planeoff = bb * HWSZ;

        #pragma unroll
        for (int p = 0; p < 4; ++p) {
            const int b = bmin + p;
            // duplicate-free reflection mask
            bool nodup;
            if (a == 0)       nodup = sw ? (sg2 > 0) : (sg1 > 0);
            else if (a == b)  nodup = (sw == 0);
            else              nodup = true;
            const bool act = (p < Wd) && nodup;
            const float w  = act ? 1.0f : 0.0f;

            const int x0 = sw ? b : a;
            const int y0 = sw ? a : b;
            const int x  = sg1 * x0;               // h - 1024
            const int y  = sg2 * y0;               // w - 1024

            const int dd = x * x + y * y;
            const bool c  = dd < TH;
            const bool pu = ((((x - 1) * (x - 1) + y * y) < TH) == c);
            const bool pd = ((((x + 1) * (x + 1) + y * y) < TH) == c);
            const bool pl = (((x * x + (y - 1) * (y - 1)) < TH) == c);
            const bool pr = (((x * x + (y + 1) * (y + 1)) < TH) == c);
            const int voff = pu ? -WW : (pd ? WW : 0);   // 0 -> grad = 0
            const int hoff = pl ? -1  : (pr ? 1  : 0);

            const int idx = (x + 1024) * WW + (y + 1024) + planeoff;
            const float o1  = __ldg(s1 + idx);
            const float o1v = __ldg(s1 + idx + voff);
            const float o1h = __ldg(s1 + idx + hoff);
            const float o2  = __ldg(s2 + idx);
            const float o2v = __ldg(s2 + idx + voff);
            const float o2h = __ldg(s2 + idx + hoff);

            const float dv = o1 - o2;
            float f = dv * dv;
            float g, t;
            g = (o1 - o1v) * 100.0f;  t = fmaf(2.0f, g, -1.0f);  f = fmaf(t, t, f);
            g = (o1 - o1h) * 100.0f;  t = fmaf(2.0f, g, -1.0f);  f = fmaf(t, t, f);
            g = (o2 - o2v) * 100.0f;  t = fmaf(2.0f, g, -1.0f);  f = fmaf(t, t, f);
            g = (o2 - o2h) * 100.0f;  t = fmaf(2.0f, g, -1.0f);  f = fmaf(t, t, f);

            lacc = fmaf(w, f, lacc);
        }
    }

    // ---- warp reduce (float) ----
    #pragma unroll
    for (int o = 16; o > 0; o >>= 1)
        lacc += __shfl_down_sync(0xffffffffu, lacc, o);

    __shared__ float sacc[WARPS_PER_BLK];
    if (lane == 0) sacc[wid] = lacc;
    __syncthreads();
    if (wid == 0 && lane < WARPS_PER_BLK) {
        lacc = sacc[lane];
        #pragma unroll
        for (int o = WARPS_PER_BLK / 2; o > 0; o >>= 1)
            lacc += __shfl_down_sync(0x0000000fu, lacc, o);
        if (lane == 0) {
            atomicAdd(&g_acc, lacc);               // one FP32 L2 atomic/block
            __threadfence();
            const unsigned int old = atomicInc(&g_done, NBLOCKS - 1u);
            if (old == NBLOCKS - 1u) {             // last block finalizes
                const float tot = atomicExch(&g_acc, 0.0f);  // read + reset
                out[0] = tot * inv;
            }
        }
    }
}

extern "C" void kernel_launch(void* const* d_in, const int* in_sizes, int n_in,
                              void* d_out, int out_size)
{
    (void)in_sizes; (void)n_in; (void)out_size;
    const float* s1 = (const float*)d_in[0];
    const float* s2 = (const float*)d_in[1];
    float* out = (float*)d_out;

    // nb (boundary-pixel count) is a pure function of the geometry: compute
    // exactly on host with the same integer logic.
    long long nb = 0;
    for (int a = -512; a <= 512; ++a) {
        const int lo = LOQ - a * a;
        const int hi = HIQ - a * a;
        if (hi < 0) continue;
        int bmax = (int)floor(sqrt((double)hi));
        while ((long long)(bmax + 1) * (bmax + 1) <= hi) ++bmax;
        while ((long long)bmax * bmax > hi) --bmax;
        int bmin = 0;
        if (lo > 0) {
            bmin = (int)ceil(sqrt((double)lo));
            while ((long long)bmin * bmin < lo) ++bmin;
            while (bmin > 0 && (long long)(bmin - 1) * (bmin - 1) >= lo) --bmin;
        }
        if (bmax >= bmin)
            nb += (lo > 0) ? 2LL * (bmax - bmin + 1) : (2LL * bmax + 1);
    }
    const float inv = (float)(1.0 / (4.0 * (double)nb));

    ibl_kernel<<<NBLOCKS, WARPS_PER_BLK * 32>>>(s1, s2, out, inv);
}

// round 9
// speedup vs baseline: 1.6570x; 1.3092x over previous
#include <cuda_runtime.h>
#include <math.h>

// InterfaceBoundaryLoss: B=4, H=W=2048, DX=DY=0.01, E_IN=2, CONST=1, WEIGHT=1.
//
// With a=h-1024, b=w-1024, dd=a^2+b^2:
//   interface <=> dd <  262144           (r < 512)
//   boundary  <=> 261122 <= dd <= 263168 (|r-512| < 1)
//
// R8 = R7 (octant symmetry, 91 blocks x 4 warps, host-side nb, float atomic
// + ticket + exch tail) with three targeted trims:
//   - branchless sqrt fixup (selects, no BSSY/BSYNC loops in prelude)
//   - dead unroll slots clamp to b=bmin (re-touch resident lines; no extra
//     L2/DRAM line fetches for the w=0 work)
//   - __threadfence removed: atomicAdd's RETURN value is folded (opaquely)
//     into the ticket address -> add is globally performed before the ticket,
//     without a GPU-scope membar

#define WW 2048
#define HWSZ (2048 * 2048)
#define TH  262144
#define LOQ 261122
#define HIQ 263168
#define NROWS 363
#define WARPS_PER_BLK 4
#define NBLOCKS ((NROWS + WARPS_PER_BLK - 1) / WARPS_PER_BLK)   // 91

__device__ float        g_acc  = 0.0f;
__device__ unsigned int g_done = 0u;

__global__ void __launch_bounds__(WARPS_PER_BLK * 32)
ibl_kernel(const float* __restrict__ s1, const float* __restrict__ s2,
           float* __restrict__ out, float inv)
{
    const int tid  = threadIdx.x;
    const int lane = tid & 31;
    const int wid  = tid >> 5;
    const int a    = blockIdx.x * WARPS_PER_BLK + wid;   // octant row

    float lacc = 0.0f;

    if (a < NROWS) {
        const int lo = LOQ - a * a;            // > 0 for a <= 362
        const int hi = HIQ - a * a;

        // branchless integer sqrt: sqrtf is within +-1 of the true root
        int bmax = (int)sqrtf((float)hi);
        bmax += ((bmax + 1) * (bmax + 1) <= hi);
        bmax -= (bmax * bmax > hi);
        int bminr = (int)sqrtf((float)lo);
        bminr += (bminr * bminr < lo);
        bminr -= ((bminr - 1) * (bminr - 1) >= lo);
        const int bmin = (bminr > a) ? bminr : a;   // octant: b >= a
        const int Wd   = bmax - bmin + 1;           // 1..4

        const int refl = lane & 7;
        const int bb   = lane >> 3;                 // batch 0..3
        const int sg1  = (refl & 1) ? -1 : 1;
        const int sg2  = (refl & 2) ? -1 : 1;
        const int sw   = refl >> 2;

        const int planeoff = bb * HWSZ;

        #pragma unroll
        for (int p = 0; p < 4; ++p) {
            const bool live = (p < Wd);
            const int  b    = bmin + (live ? p : 0);   // clamp dead slots
            // duplicate-free reflection mask
            bool nodup;
            if (a == 0)       nodup = sw ? (sg2 > 0) : (sg1 > 0);
            else if (a == b)  nodup = (sw == 0);
            else              nodup = true;
            const float w = (live && nodup) ? 1.0f : 0.0f;

            const int x0 = sw ? b : a;
            const int y0 = sw ? a : b;
            const int x  = sg1 * x0;               // h - 1024
            const int y  = sg2 * y0;               // w - 1024

            const int dd = x * x + y * y;
            const bool c  = dd < TH;
            const bool pu = ((((x - 1) * (x - 1) + y * y) < TH) == c);
            const bool pd = ((((x + 1) * (x + 1) + y * y) < TH) == c);
            const bool pl = (((x * x + (y - 1) * (y - 1)) < TH) == c);
            const bool pr = (((x * x + (y + 1) * (y + 1)) < TH) == c);
            const int voff = pu ? -WW : (pd ? WW : 0);   // 0 -> grad = 0
            const int hoff = pl ? -1  : (pr ? 1  : 0);

            const int idx = (x + 1024) * WW + (y + 1024) + planeoff;
            const float o1  = __ldg(s1 + idx);
            const float o1v = __ldg(s1 + idx + voff);
            const float o1h = __ldg(s1 + idx + hoff);
            const float o2  = __ldg(s2 + idx);
            const float o2v = __ldg(s2 + idx + voff);
            const float o2h = __ldg(s2 + idx + hoff);

            const float dv = o1 - o2;
            float f = dv * dv;
            float g, t;
            g = (o1 - o1v) * 100.0f;  t = fmaf(2.0f, g, -1.0f);  f = fmaf(t, t, f);
            g = (o1 - o1h) * 100.0f;  t = fmaf(2.0f, g, -1.0f);  f = fmaf(t, t, f);
            g = (o2 - o2v) * 100.0f;  t = fmaf(2.0f, g, -1.0f);  f = fmaf(t, t, f);
            g = (o2 - o2h) * 100.0f;  t = fmaf(2.0f, g, -1.0f);  f = fmaf(t, t, f);

            lacc = fmaf(w, f, lacc);
        }
    }

    // ---- warp reduce (float) ----
    #pragma unroll
    for (int o = 16; o > 0; o >>= 1)
        lacc += __shfl_down_sync(0xffffffffu, lacc, o);

    __shared__ float sacc[WARPS_PER_BLK];
    if (lane == 0) sacc[wid] = lacc;
    __syncthreads();
    if (wid == 0 && lane < WARPS_PER_BLK) {
        lacc = sacc[lane];
        #pragma unroll
        for (int o = WARPS_PER_BLK / 2; o > 0; o >>= 1)
            lacc += __shfl_down_sync(0x0000000fu, lacc, o);
        if (lane == 0) {
            // Consume the atomic's return value: when it arrives, the add is
            // globally performed at L2. Fold it (opaquely, ==0) into the
            // ticket address so the ticket cannot be reordered before it.
            const float old = atomicAdd(&g_acc, lacc);
            unsigned int zero;
            asm volatile("{ .reg .b32 t; mov.b32 t, %1; and.b32 %0, t, 0; }"
                         : "=r"(zero) : "f"(old));
            unsigned int* done = &g_done + zero;   // == &g_done, data-dependent
            const unsigned int o = atomicInc(done, NBLOCKS - 1u);
            if (o == NBLOCKS - 1u) {               // last block finalizes
                const float tot = atomicExch(&g_acc, 0.0f);  // read + reset
                out[0] = tot * inv;
            }
        }
    }
}

extern "C" void kernel_launch(void* const* d_in, const int* in_sizes, int n_in,
                              void* d_out, int out_size)
{
    (void)in_sizes; (void)n_in; (void)out_size;
    const float* s1 = (const float*)d_in[0];
    const float* s2 = (const float*)d_in[1];
    float* out = (float*)d_out;

    // nb (boundary-pixel count) is a pure function of the geometry: compute
    // exactly on host with the same integer logic.
    long long nb = 0;
    for (int a = -512; a <= 512; ++a) {
        const int lo = LOQ - a * a;
        const int hi = HIQ - a * a;
        if (hi < 0) continue;
        int bmax = (int)floor(sqrt((double)hi));
        while ((long long)(bmax + 1) * (bmax + 1) <= hi) ++bmax;
        while ((long long)bmax * bmax > hi) --bmax;
        int bmin = 0;
        if (lo > 0) {
            bmin = (int)ceil(sqrt((double)lo));
            while ((long long)bmin * bmin < lo) ++bmin;
            while (bmin > 0 && (long long)(bmin - 1) * (bmin - 1) >= lo) --bmin;
        }
        if (bmax >= bmin)
            nb += (lo > 0) ? 2LL * (bmax - bmin + 1) : (2LL * bmax + 1);
    }
    const float inv = (float)(1.0 / (4.0 * (double)nb));

    ibl_kernel<<<NBLOCKS, WARPS_PER_BLK * 32>>>(s1, s2, out, inv);
}